// round 5
// baseline (speedup 1.0000x reference)
#include <cuda_runtime.h>
#include <cstdint>

// Problem constants
#define BB   8
#define ND   12288
#define NU   49152
#define CI   64
#define CO   32
#define SP   9
#define NNZE 147456
#define KTOT (SP * CI)   // 576

// Scratch (device globals — no runtime allocation allowed)
__device__ __align__(256) float g_pooled[(size_t)BB * NU * CI];   // 100.7 MB
__device__ int    g_cnt[NU];
__device__ int    g_off[NU + 1];
__device__ int    g_wp[NU];
__device__ int    g_eid[NNZE];
__device__ __align__(16) float2 g_wpack[SP * (CI / 2) * CO];  // [s][kc2][o]

// ---------------------------------------------------------------------------
// Launch 0: zero counts + weight prepack (independent outputs, one kernel)
// Wp[(s*32 + kc2)*32 + o] = (W[o][s*64+2kc2], W[o][s*64+2kc2+1])
// ---------------------------------------------------------------------------
__global__ void init_misc(const float* __restrict__ weight) {
    int i = blockIdx.x * blockDim.x + threadIdx.x;
    if (i < NU) g_cnt[i] = 0;
    if (i < SP * 32 * CO) {
        int o   = i & 31;
        int kc2 = (i >> 5) & 31;
        int s   = i >> 10;
        const float* src = weight + o * KTOT + s * CI + 2 * kc2;
        g_wpack[i] = make_float2(__ldg(src), __ldg(src + 1));
    }
}

// ---------------------------------------------------------------------------
// Launch 1: histogram of rows
// ---------------------------------------------------------------------------
__global__ void hist_rows(const int* __restrict__ rows) {
    int e = blockIdx.x * blockDim.x + threadIdx.x;
    if (e < NNZE) atomicAdd(&g_cnt[__ldg(rows + e)], 1);
}

// ---------------------------------------------------------------------------
// Launch 2: single-block scan of counts + CSR fill
// ---------------------------------------------------------------------------
__global__ void __launch_bounds__(1024)
scan_fill(const int* __restrict__ rows) {
    __shared__ int warp_sums[32];
    const int t = threadIdx.x, lane = t & 31, w = t >> 5;
    const int base = t * (NU / 1024);

    int local = 0;
#pragma unroll 4
    for (int j = 0; j < NU / 1024; j++) local += g_cnt[base + j];

    int v = local;
#pragma unroll
    for (int d = 1; d < 32; d <<= 1) {
        int n = __shfl_up_sync(0xffffffffu, v, d);
        if (lane >= d) v += n;
    }
    if (lane == 31) warp_sums[w] = v;
    __syncthreads();
    if (w == 0) {
        int s = warp_sums[lane];
#pragma unroll
        for (int d = 1; d < 32; d <<= 1) {
            int n = __shfl_up_sync(0xffffffffu, s, d);
            if (lane >= d) s += n;
        }
        warp_sums[lane] = s;
    }
    __syncthreads();

    int run = (v - local) + (w > 0 ? warp_sums[w - 1] : 0);
#pragma unroll 4
    for (int j = 0; j < NU / 1024; j++) {
        int c = g_cnt[base + j];
        g_off[base + j] = run;
        g_wp[base + j]  = run;
        run += c;
    }
    if (t == 1023) g_off[NU] = run;
    __syncthreads();   // g_wp visible block-wide (global fence within block)

    // Fill entry lists
    for (int e = t; e < NNZE; e += 1024) {
        int p = atomicAdd(&g_wp[__ldg(rows + e)], 1);
        g_eid[p] = e;
    }
}

// ---------------------------------------------------------------------------
// Launch 3: gather-pool. thread = (row, c4). fp32 accumulate over entries,
// all 8 batches in registers, float4 stores.
// ---------------------------------------------------------------------------
__global__ void __launch_bounds__(256)
gather_pool(const float* __restrict__ x,
            const int*   __restrict__ cols,
            const float* __restrict__ vals) {
    int gt  = blockIdx.x * blockDim.x + threadIdx.x;
    int row = gt >> 4;
    int c4  = gt & 15;
    if (row >= NU) return;

    int s = g_off[row];
    int e = g_off[row + 1];

    float4 acc[BB];
#pragma unroll
    for (int b = 0; b < BB; b++) acc[b] = make_float4(0.f, 0.f, 0.f, 0.f);

    for (int i = s; i < e; i++) {
        int   eid = g_eid[i];
        int   col = __ldg(cols + eid);
        float v   = __ldg(vals + eid);
        const float4* xp = reinterpret_cast<const float4*>(x) + (size_t)col * 16 + c4;
#pragma unroll
        for (int b = 0; b < BB; b++) {
            float4 xv = __ldg(xp + (size_t)b * (ND * 16));
            acc[b].x += v * xv.x; acc[b].y += v * xv.y;
            acc[b].z += v * xv.z; acc[b].w += v * xv.w;
        }
    }

    float4* pp = reinterpret_cast<float4*>(g_pooled) + (size_t)row * 16 + c4;
#pragma unroll
    for (int b = 0; b < BB; b++)
        pp[(size_t)b * (NU * 16)] = acc[b];
}

// ---------------------------------------------------------------------------
// Launch 4: fused spiral gather + GEMM + bias + relu, cp.async pipelined.
// Double-buffered G tiles; gather for stage s+2 overlaps compute of s+1.
// Inner product: paired fma.rn.f32x2, zero pack/unpack movs.
// ---------------------------------------------------------------------------
#define TILE_R 128
#define GPAD   68                       // 272B row stride (16B aligned)
#define SM_WS  0                        // 73728 B packed weight pairs
#define SM_SG  (SP * 32 * CO * 8)       // 73728: spiral indices, 4608 B
#define SM_G0  (SM_SG + TILE_R * SP * 4)        // 78336
#define SM_G1  (SM_G0 + TILE_R * GPAD * 4)      // 113152
#define SM_TOT (SM_G1 + TILE_R * GPAD * 4)      // 147968 B

__device__ __forceinline__ uint32_t smem_u32(const void* p) {
    uint32_t a;
    asm("{ .reg .u64 t; cvta.to.shared.u64 t, %1; cvt.u32.u64 %0, t; }" : "=r"(a) : "l"(p));
    return a;
}
__device__ __forceinline__ void cp16(uint32_t dst, const void* src) {
    asm volatile("cp.async.cg.shared.global [%0], [%1], 16;" :: "r"(dst), "l"(src));
}
#define CP_COMMIT() asm volatile("cp.async.commit_group;" ::: "memory")
#define CP_WAIT(n)  asm volatile("cp.async.wait_group %0;" :: "n"(n) : "memory")

__device__ __forceinline__ void ffma2(unsigned long long& acc,
                                      unsigned long long a2,
                                      unsigned long long b2) {
    asm("fma.rn.f32x2 %0, %1, %2, %0;" : "+l"(acc) : "l"(a2), "l"(b2));
}
__device__ __forceinline__ float2 unpack2(unsigned long long v) {
    float2 r;
    asm("mov.b64 {%0, %1}, %2;" : "=f"(r.x), "=f"(r.y) : "l"(v));
    return r;
}

__global__ void __launch_bounds__(256, 1)
spiral_pipe(const int*   __restrict__ sidx,
            const float* __restrict__ bias,
            float*       __restrict__ out) {
    extern __shared__ char smraw[];
    float* smf = reinterpret_cast<float*>(smraw);
    uint32_t smb = smem_u32(smraw);

    const int tid = threadIdx.x;
    const int b   = blockIdx.y;
    const int n0  = blockIdx.x * TILE_R;
    const char* pooledB =
        reinterpret_cast<const char*>(g_pooled) + (size_t)b * NU * 256;
    int* Sg = reinterpret_cast<int*>(smraw + SM_SG);

    // Stage W (cp.async, joins group 0)
    {
        const char* wp = reinterpret_cast<const char*>(g_wpack);
        for (int i = tid; i < SP * 32 * CO * 8 / 16; i += 256)
            cp16(smb + SM_WS + i * 16, wp + i * 16);
    }
    // Spiral indices for this block: 1152 contiguous ints
    for (int i = tid; i < TILE_R * SP; i += 256)
        Sg[i] = __ldg(sidx + (size_t)n0 * SP + i);
    __syncthreads();   // Sg ready for gathers

    // Gather one stage into buffer: 2048 cp16 (8/thread), 16 threads/row
    auto gather = [&](int s, int buf) {
        uint32_t gb = smb + (buf ? SM_G1 : SM_G0);
#pragma unroll
        for (int it = 0; it < 8; it++) {
            int i   = it * 256 + tid;
            int rl  = i >> 4;
            int c16 = i & 15;
            int idx = Sg[rl * SP + s];
            cp16(gb + rl * (GPAD * 4) + c16 * 16,
                 pooledB + (size_t)idx * 256 + c16 * 16);
        }
    };

    gather(0, 0);
    CP_COMMIT();            // group: W + s0
    gather(1, 1);
    CP_COMMIT();            // group: s1

    const int to = tid & 7;     // out group o0 = to*4
    const int tr = tid >> 3;    // rows tr*4 .. tr*4+3

    unsigned long long acc[4][4];
#pragma unroll
    for (int i = 0; i < 4; i++)
#pragma unroll
        for (int j = 0; j < 4; j++) acc[i][j] = 0ull;

#pragma unroll 1
    for (int s = 0; s < SP; s++) {
        if (s == SP - 1) CP_WAIT(0); else CP_WAIT(1);
        __syncthreads();    // stage-s data visible to all

        const ulonglong2* ws2 =
            reinterpret_cast<const ulonglong2*>(smf) + (size_t)s * 512 + to * 2;
        const float* gk = smf + ((s & 1) ? SM_G1 : SM_G0) / 4 + tr * 4 * GPAD;

#pragma unroll 4
        for (int kc2 = 0; kc2 < 32; kc2 += 2) {
            ulonglong2 wA0 = ws2[(size_t)kc2 * 16];
            ulonglong2 wA1 = ws2[(size_t)kc2 * 16 + 1];
            ulonglong2 wB0 = ws2[(size_t)(kc2 + 1) * 16];
            ulonglong2 wB1 = ws2[(size_t)(kc2 + 1) * 16 + 1];
#pragma unroll
            for (int i = 0; i < 4; i++) {
                ulonglong2 g = *reinterpret_cast<const ulonglong2*>(gk + i * GPAD + 2 * kc2);
                ffma2(acc[i][0], g.x, wA0.x);
                ffma2(acc[i][1], g.x, wA0.y);
                ffma2(acc[i][2], g.x, wA1.x);
                ffma2(acc[i][3], g.x, wA1.y);
                ffma2(acc[i][0], g.y, wB0.x);
                ffma2(acc[i][1], g.y, wB0.y);
                ffma2(acc[i][2], g.y, wB1.x);
                ffma2(acc[i][3], g.y, wB1.y);
            }
        }

        __syncthreads();    // all threads done reading buf (s&1)
        if (s + 2 < SP) {
            gather(s + 2, s & 1);
            CP_COMMIT();
        }
    }

    // Epilogue: horizontal add of k-parity halves, bias + relu, float4 store
    const int o0 = to * 4;
    float4 bv = *reinterpret_cast<const float4*>(bias + o0);
#pragma unroll
    for (int i = 0; i < 4; i++) {
        float2 a0 = unpack2(acc[i][0]);
        float2 a1 = unpack2(acc[i][1]);
        float2 a2 = unpack2(acc[i][2]);
        float2 a3 = unpack2(acc[i][3]);
        float4 r;
        r.x = fmaxf(a0.x + a0.y + bv.x, 0.f);
        r.y = fmaxf(a1.x + a1.y + bv.y, 0.f);
        r.z = fmaxf(a2.x + a2.y + bv.z, 0.f);
        r.w = fmaxf(a3.x + a3.y + bv.w, 0.f);
        int n = n0 + tr * 4 + i;
        *reinterpret_cast<float4*>(out + ((size_t)b * NU + n) * CO + o0) = r;
    }
}

// ---------------------------------------------------------------------------
// Launch (exactly 5 kernels per call)
// ---------------------------------------------------------------------------
extern "C" void kernel_launch(void* const* d_in, const int* in_sizes, int n_in,
                              void* d_out, int out_size) {
    const float* x        = (const float*)d_in[0];
    const int*   up_rows  = (const int*)  d_in[1];
    const int*   up_cols  = (const int*)  d_in[2];
    const float* up_vals  = (const float*)d_in[3];
    const int*   sidx     = (const int*)  d_in[4];
    const float* weight   = (const float*)d_in[5];
    const float* bias     = (const float*)d_in[6];
    float*       out      = (float*)d_out;

    init_misc<<<(NU + 255) / 256, 256>>>(weight);
    hist_rows<<<(NNZE + 255) / 256, 256>>>(up_rows);
    scan_fill<<<1, 1024>>>(up_rows);
    gather_pool<<<(NU * 16) / 256, 256>>>(x, up_cols, up_vals);

    cudaFuncSetAttribute(spiral_pipe,
                         cudaFuncAttributeMaxDynamicSharedMemorySize, SM_TOT);
    dim3 grid(NU / TILE_R, BB);
    spiral_pipe<<<grid, 256, SM_TOT>>>(sidx, bias, out);
}

// round 6
// speedup vs baseline: 1.7888x; 1.7888x over previous
#include <cuda_runtime.h>
#include <cuda_bf16.h>
#include <cstdint>

// Problem constants
#define BB   8
#define ND   12288
#define NU   49152
#define CI   64
#define CO   32
#define SP   9
#define NNZE 147456
#define KTOT (SP * CI)   // 576

// ---------------------------------------------------------------------------
// Device scratch
// ---------------------------------------------------------------------------
__device__ int g_cnt[NU];
__device__ int g_off[NU + 1];
__device__ int g_wp[NU];
__device__ int g_eid[NNZE];
// pooled, split bf16 planes: [b][row][64ch], each row 128B
__device__ __align__(256) unsigned short g_ph[(size_t)BB * NU * CI];
__device__ __align__(256) unsigned short g_pl[(size_t)BB * NU * CI];
// weight, split bf16, [s][n=32][k=64] with 16B-unit XOR swizzle, ldmatrix-ready
__device__ __align__(256) unsigned short g_wh[SP * CO * CI];
__device__ __align__(256) unsigned short g_wl[SP * CO * CI];

// ---------------------------------------------------------------------------
// Launch 0: zero counts + weight split/swizzle prepack
// ---------------------------------------------------------------------------
__global__ void init_misc(const float* __restrict__ weight) {
    int i = blockIdx.x * blockDim.x + threadIdx.x;
    if (i < NU) g_cnt[i] = 0;
    if (i < SP * CO * CI) {
        int k = i & 63;
        int n = (i >> 6) & 31;
        int s = i >> 11;
        float v = __ldg(weight + n * KTOT + s * CI + k);
        __nv_bfloat16 hi = __float2bfloat16(v);
        __nv_bfloat16 lo = __float2bfloat16(v - __bfloat162float(hi));
        int unit = k >> 3;                 // 16B unit within 128B row
        int within = (k * 2) & 15;
        int byte = s * 4096 + n * 128 + ((unit ^ (n & 7)) << 4) + within;
        g_wh[byte >> 1] = __bfloat16_as_ushort(hi);
        g_wl[byte >> 1] = __bfloat16_as_ushort(lo);
    }
}

// ---------------------------------------------------------------------------
// Launch 1: histogram of rows
// ---------------------------------------------------------------------------
__global__ void hist_rows(const int* __restrict__ rows) {
    int e = blockIdx.x * blockDim.x + threadIdx.x;
    if (e < NNZE) atomicAdd(&g_cnt[__ldg(rows + e)], 1);
}

// ---------------------------------------------------------------------------
// Launch 2: single-block scan + CSR fill
// ---------------------------------------------------------------------------
__global__ void __launch_bounds__(1024)
scan_fill(const int* __restrict__ rows) {
    __shared__ int warp_sums[32];
    const int t = threadIdx.x, lane = t & 31, w = t >> 5;
    const int base = t * (NU / 1024);

    int local = 0;
#pragma unroll 4
    for (int j = 0; j < NU / 1024; j++) local += g_cnt[base + j];

    int v = local;
#pragma unroll
    for (int d = 1; d < 32; d <<= 1) {
        int n = __shfl_up_sync(0xffffffffu, v, d);
        if (lane >= d) v += n;
    }
    if (lane == 31) warp_sums[w] = v;
    __syncthreads();
    if (w == 0) {
        int s = warp_sums[lane];
#pragma unroll
        for (int d = 1; d < 32; d <<= 1) {
            int n = __shfl_up_sync(0xffffffffu, s, d);
            if (lane >= d) s += n;
        }
        warp_sums[lane] = s;
    }
    __syncthreads();

    int run = (v - local) + (w > 0 ? warp_sums[w - 1] : 0);
#pragma unroll 4
    for (int j = 0; j < NU / 1024; j++) {
        int c = g_cnt[base + j];
        g_off[base + j] = run;
        g_wp[base + j]  = run;
        run += c;
    }
    if (t == 1023) g_off[NU] = run;
    __syncthreads();

    for (int e = t; e < NNZE; e += 1024) {
        int p = atomicAdd(&g_wp[__ldg(rows + e)], 1);
        g_eid[p] = e;
    }
}

// ---------------------------------------------------------------------------
// Launch 3: gather-pool -> bf16 hi/lo planes.
// ---------------------------------------------------------------------------
__global__ void __launch_bounds__(256)
gather_pool(const float* __restrict__ x,
            const int*   __restrict__ cols,
            const float* __restrict__ vals) {
    int gt  = blockIdx.x * blockDim.x + threadIdx.x;
    int row = gt >> 4;
    int c4  = gt & 15;
    if (row >= NU) return;

    int s = g_off[row];
    int e = g_off[row + 1];

    float4 acc[BB];
#pragma unroll
    for (int b = 0; b < BB; b++) acc[b] = make_float4(0.f, 0.f, 0.f, 0.f);

    for (int i = s; i < e; i++) {
        int   eid = g_eid[i];
        int   col = __ldg(cols + eid);
        float v   = __ldg(vals + eid);
        const float4* xp = reinterpret_cast<const float4*>(x) + (size_t)col * 16 + c4;
#pragma unroll
        for (int b = 0; b < BB; b++) {
            float4 xv = __ldg(xp + (size_t)b * (ND * 16));
            acc[b].x += v * xv.x; acc[b].y += v * xv.y;
            acc[b].z += v * xv.z; acc[b].w += v * xv.w;
        }
    }

#pragma unroll
    for (int b = 0; b < BB; b++) {
        float f[4] = {acc[b].x, acc[b].y, acc[b].z, acc[b].w};
        ushort4 h, l;
        unsigned short* hp = &h.x;
        unsigned short* lp = &l.x;
#pragma unroll
        for (int j = 0; j < 4; j++) {
            __nv_bfloat16 hb = __float2bfloat16(f[j]);
            __nv_bfloat16 lb = __float2bfloat16(f[j] - __bfloat162float(hb));
            hp[j] = __bfloat16_as_ushort(hb);
            lp[j] = __bfloat16_as_ushort(lb);
        }
        size_t off = ((size_t)b * NU + row) * CI + c4 * 4;
        *reinterpret_cast<ushort4*>(g_ph + off) = h;
        *reinterpret_cast<ushort4*>(g_pl + off) = l;
    }
}

// ---------------------------------------------------------------------------
// Launch 4: fused spiral gather + mma.sync bf16-split GEMM + bias + relu.
// Block: 128 rows x 32 outs, 8 warps (warp w: rows w*16..w*16+15).
// cp.async double-buffered A (hi/lo planes, XOR-swizzled rows);
// W resident in smem; ldmatrix.x4 frags; 3-term split accumulation.
// ---------------------------------------------------------------------------
#define TILE_R 128
#define SM_W   0                         // 73728 B (hi 36864 | lo 36864)
#define SM_SG  (SP * 4096 * 2)           // 73728: spiral indices, 4608 B
#define SM_A   (SM_SG + TILE_R * SP * 4) // 78336 (128B aligned)
#define SM_TOT (SM_A + 2 * 32768)        // 143872 B

__device__ __forceinline__ uint32_t smem_u32(const void* p) {
    uint32_t a;
    asm("{ .reg .u64 t; cvta.to.shared.u64 t, %1; cvt.u32.u64 %0, t; }" : "=r"(a) : "l"(p));
    return a;
}
__device__ __forceinline__ void cp16(uint32_t dst, const void* src) {
    asm volatile("cp.async.cg.shared.global [%0], [%1], 16;" :: "r"(dst), "l"(src));
}
#define CP_COMMIT() asm volatile("cp.async.commit_group;" ::: "memory")
#define CP_WAIT(n)  asm volatile("cp.async.wait_group %0;" :: "n"(n) : "memory")

__device__ __forceinline__ void ldsm4(uint32_t addr, uint32_t& r0, uint32_t& r1,
                                      uint32_t& r2, uint32_t& r3) {
    asm volatile("ldmatrix.sync.aligned.m8n8.x4.shared.b16 {%0,%1,%2,%3}, [%4];"
                 : "=r"(r0), "=r"(r1), "=r"(r2), "=r"(r3) : "r"(addr));
}
__device__ __forceinline__ void mma_bf16(float* c, uint32_t a0, uint32_t a1,
                                         uint32_t a2, uint32_t a3,
                                         uint32_t b0, uint32_t b1) {
    asm volatile(
        "mma.sync.aligned.m16n8k16.row.col.f32.bf16.bf16.f32 "
        "{%0,%1,%2,%3}, {%4,%5,%6,%7}, {%8,%9}, {%0,%1,%2,%3};"
        : "+f"(c[0]), "+f"(c[1]), "+f"(c[2]), "+f"(c[3])
        : "r"(a0), "r"(a1), "r"(a2), "r"(a3), "r"(b0), "r"(b1));
}

__global__ void __launch_bounds__(256, 1)
spiral_mma(const int*   __restrict__ sidx,
           const float* __restrict__ bias,
           float*       __restrict__ out) {
    extern __shared__ char smraw[];
    uint32_t smb = smem_u32(smraw);

    const int tid  = threadIdx.x;
    const int wid  = tid >> 5;
    const int lane = tid & 31;
    const int b    = blockIdx.y;
    const int n0   = blockIdx.x * TILE_R;

    const char* phB = reinterpret_cast<const char*>(g_ph) + (size_t)b * NU * 128;
    const char* plB = reinterpret_cast<const char*>(g_pl) + (size_t)b * NU * 128;
    int* Sg = reinterpret_cast<int*>(smraw + SM_SG);

    // Stage W hi/lo (pre-swizzled) via cp.async — joins group with s=0
    {
        const char* wh = reinterpret_cast<const char*>(g_wh);
        const char* wl = reinterpret_cast<const char*>(g_wl);
        for (int i = tid; i < SP * 4096 / 16; i += 256) {
            cp16(smb + SM_W + i * 16, wh + i * 16);
            cp16(smb + SM_W + SP * 4096 + i * 16, wl + i * 16);
        }
    }
    for (int i = tid; i < TILE_R * SP; i += 256)
        Sg[i] = __ldg(sidx + (size_t)n0 * SP + i);
    __syncthreads();   // Sg ready

    // Gather one stage: 2048 cp16 (hi 1024 + lo 1024), XOR-swizzled rows
    auto gather = [&](int s, int buf) {
        uint32_t ab = smb + SM_A + buf * 32768;
#pragma unroll
        for (int it = 0; it < 8; it++) {
            int i     = it * 256 + tid;
            int plane = i >> 10;
            int rem   = i & 1023;
            int r     = rem >> 3;
            int u     = rem & 7;
            int idx   = Sg[r * SP + s];
            const char* src = (plane ? plB : phB) + (size_t)idx * 128 + u * 16;
            cp16(ab + plane * 16384 + r * 128 + ((u ^ (r & 7)) << 4), src);
        }
    };

    gather(0, 0);
    CP_COMMIT();
    gather(1, 1);
    CP_COMMIT();

    float acc[4][4];
#pragma unroll
    for (int i = 0; i < 4; i++)
#pragma unroll
        for (int j = 0; j < 4; j++) acc[i][j] = 0.f;

    // Per-thread ldmatrix geometry (fixed across k-steps except unit)
    const int m8  = lane >> 3;      // matrix id 0..3
    const int t8  = lane & 7;
    const int arow = wid * 16 + (m8 & 1) * 8 + t8;     // A row for this thread
    const int mk   = m8 >> 1;                          // k-half within kstep

#pragma unroll 1
    for (int s = 0; s < SP; s++) {
        if (s == SP - 1) CP_WAIT(0); else CP_WAIT(1);
        __syncthreads();

        uint32_t abase = smb + SM_A + (s & 1) * 32768;
        uint32_t wbase = smb + SM_W + s * 4096;

#pragma unroll
        for (int ks = 0; ks < 4; ks++) {
            int unit = 2 * ks + mk;
            // A frags (hi, lo)
            uint32_t aaddr = abase + arow * 128 + ((unit ^ (arow & 7)) << 4);
            uint32_t ah[4], al[4];
            ldsm4(aaddr,         ah[0], ah[1], ah[2], ah[3]);
            ldsm4(aaddr + 16384, al[0], al[1], al[2], al[3]);
            // B frags: nb=0 -> n0-15, nb=1 -> n16-31 (hi and lo planes)
            uint32_t bh0[4], bh1[4], bl0[4], bl1[4];
#pragma unroll
            for (int nb = 0; nb < 2; nb++) {
                int nrow = nb * 16 + (m8 & 1) * 8 + t8;
                uint32_t baddr = wbase + nrow * 128 + ((unit ^ (nrow & 7)) << 4);
                uint32_t* bh = nb ? bh1 : bh0;
                uint32_t* bl = nb ? bl1 : bl0;
                ldsm4(baddr,             bh[0], bh[1], bh[2], bh[3]);
                ldsm4(baddr + SP * 4096, bl[0], bl[1], bl[2], bl[3]);
            }
            // 4 n-tiles x 3 split terms
            mma_bf16(acc[0], ah[0], ah[1], ah[2], ah[3], bh0[0], bh0[2]);
            mma_bf16(acc[1], ah[0], ah[1], ah[2], ah[3], bh0[1], bh0[3]);
            mma_bf16(acc[2], ah[0], ah[1], ah[2], ah[3], bh1[0], bh1[2]);
            mma_bf16(acc[3], ah[0], ah[1], ah[2], ah[3], bh1[1], bh1[3]);
            mma_bf16(acc[0], al[0], al[1], al[2], al[3], bh0[0], bh0[2]);
            mma_bf16(acc[1], al[0], al[1], al[2], al[3], bh0[1], bh0[3]);
            mma_bf16(acc[2], al[0], al[1], al[2], al[3], bh1[0], bh1[2]);
            mma_bf16(acc[3], al[0], al[1], al[2], al[3], bh1[1], bh1[3]);
            mma_bf16(acc[0], ah[0], ah[1], ah[2], ah[3], bl0[0], bl0[2]);
            mma_bf16(acc[1], ah[0], ah[1], ah[2], ah[3], bl0[1], bl0[3]);
            mma_bf16(acc[2], ah[0], ah[1], ah[2], ah[3], bl1[0], bl1[2]);
            mma_bf16(acc[3], ah[0], ah[1], ah[2], ah[3], bl1[1], bl1[3]);
        }

        __syncthreads();   // buf (s&1) fully consumed
        if (s + 2 < SP) {
            gather(s + 2, s & 1);
            CP_COMMIT();
        }
    }

    // Epilogue: C frag (m16n8): c0,c1 -> row lane/4, cols 2*(lane%4)+{0,1};
    // c2,c3 -> row+8. bias + relu, float2 stores.
    const int r0  = wid * 16 + (lane >> 2);
    const int col = (lane & 3) * 2;
    float* po0 = out + ((size_t)b * NU + n0 + r0) * CO;
    float* po1 = po0 + 8 * CO;
#pragma unroll
    for (int nt = 0; nt < 4; nt++) {
        int o = nt * 8 + col;
        float b0 = __ldg(bias + o), b1 = __ldg(bias + o + 1);
        float2 v0 = make_float2(fmaxf(acc[nt][0] + b0, 0.f), fmaxf(acc[nt][1] + b1, 0.f));
        float2 v1 = make_float2(fmaxf(acc[nt][2] + b0, 0.f), fmaxf(acc[nt][3] + b1, 0.f));
        *reinterpret_cast<float2*>(po0 + o) = v0;
        *reinterpret_cast<float2*>(po1 + o) = v1;
    }
}

// ---------------------------------------------------------------------------
// Launch (5 kernels)
// ---------------------------------------------------------------------------
extern "C" void kernel_launch(void* const* d_in, const int* in_sizes, int n_in,
                              void* d_out, int out_size) {
    const float* x        = (const float*)d_in[0];
    const int*   up_rows  = (const int*)  d_in[1];
    const int*   up_cols  = (const int*)  d_in[2];
    const float* up_vals  = (const float*)d_in[3];
    const int*   sidx     = (const int*)  d_in[4];
    const float* weight   = (const float*)d_in[5];
    const float* bias     = (const float*)d_in[6];
    float*       out      = (float*)d_out;

    init_misc<<<(NU + 255) / 256, 256>>>(weight);
    hist_rows<<<(NNZE + 255) / 256, 256>>>(up_rows);
    scan_fill<<<1, 1024>>>(up_rows);
    gather_pool<<<(NU * 16) / 256, 256>>>(x, up_cols, up_vals);

    cudaFuncSetAttribute(spiral_mma,
                         cudaFuncAttributeMaxDynamicSharedMemorySize, SM_TOT);
    dim3 grid(NU / TILE_R, BB);
    spiral_mma<<<grid, 256, SM_TOT>>>(sidx, bias, out);
}